// round 4
// baseline (speedup 1.0000x reference)
#include <cuda_runtime.h>
#include <math.h>

#define Bc   16
#define Cc   3
#define Rc   512
#define Ac   512
#define Gc   4096
#define Kc   4
#define NS   41     // shifts -20..+20
#define RP   513    // padded SAT dim
#define Qc   4      // 3 channels + channel-sum

// Static scratch
__device__ float g_y[(size_t)Bc * Qc * Rc * Ac];    // row-cumsum: q=0..2 channels, q=3 chan-sum
__device__ float g_satc[(size_t)Bc * Cc * RP * RP]; // padded per-channel SAT
__device__ float g_sata[(size_t)Bc * RP * RP];      // padded channel-sum SAT

// ---- XLA ReduceWindowRewriter (base_length=16) streaming scan state -------
// prefix(16t+j) = carry(t) + seq(x[16t..16t+j]);  carry from 2-level tiled scan
// of the 32 tile totals (tiles of 16, top level of 2 sequential).
struct TiledScan {
    float acc_inner;   // seq fold within current 16-tile
    float carry;       // carry(t) for current tile (valid for t>=1)
    float accT_low;    // seq fold of T[0..t],   t in 0..15
    float accT_hi;     // seq fold of T[16..t],  t in 16..31
    float U0;          // inner1(0,15) = fold of T[0..15]
};

// process element r (0..511) with value v, returns prefix value
__device__ __forceinline__ float tscan_step(TiledScan& S, float v, int r)
{
    const int j = r & 15;
    const int t = r >> 4;
    S.acc_inner = (j == 0) ? v : __fadd_rn(S.acc_inner, v);
    float out = (t == 0) ? S.acc_inner : __fadd_rn(S.carry, S.acc_inner);
    if (j == 15) {
        float T = S.acc_inner;             // tile total
        float incT;
        if (t < 16) {
            S.accT_low = (t == 0) ? T : __fadd_rn(S.accT_low, T);
            incT = S.accT_low;
            if (t == 15) S.U0 = S.accT_low;
        } else {
            S.accT_hi = (t == 16) ? T : __fadd_rn(S.accT_hi, T);
            incT = __fadd_rn(S.U0, S.accT_hi);
        }
        S.carry = incT;                    // carry for tile t+1
    }
    return out;
}

// ---------------- K1: row-axis scans (thread per (b,q,a)) -------------------
__global__ void __launch_bounds__(256) k_rowscan(const float* __restrict__ pred)
{
    int tid = blockIdx.x * blockDim.x + threadIdx.x;
    if (tid >= Bc * Qc * Ac) return;
    const int a  = tid & (Ac - 1);
    const int qb = tid >> 9;
    const int q  = qb & 3;
    const int b  = qb >> 2;

    const float* p = pred + ((size_t)b * Cc * Rc) * Ac + a;
    float* y = g_y + (((size_t)b * Qc + q) * Rc) * Ac + a;

    TiledScan S;
    for (int r = 0; r < Rc; r++) {
        float v;
        if (q < 3) {
            v = __ldg(p + ((size_t)q * Rc + r) * Ac);
        } else {
            float v0 = __ldg(p + (size_t)r * Ac);
            float v1 = __ldg(p + ((size_t)Rc + r) * Ac);
            float v2 = __ldg(p + ((size_t)2 * Rc + r) * Ac);
            v = __fadd_rn(__fadd_rn(v0, v1), v2);   // (p0+p1)+p2
        }
        y[(size_t)r * Ac] = tscan_step(S, v, r);
    }
}

// ---------------- K2: col-axis scans into padded SATs -----------------------
__global__ void __launch_bounds__(256) k_colscan()
{
    int tid = blockIdx.x * blockDim.x + threadIdx.x;
    if (tid >= Bc * Qc * Rc) return;
    const int r  = tid & (Rc - 1);
    const int qb = tid >> 9;
    const int q  = qb & 3;
    const int b  = qb >> 2;

    const float4* src = (const float4*)(g_y + (((size_t)b * Qc + q) * Rc + r) * Ac);
    float* dst = (q < 3)
        ? g_satc + ((size_t)(b * Cc + q)) * RP * RP + (size_t)(r + 1) * RP + 1
        : g_sata + ((size_t)b) * RP * RP + (size_t)(r + 1) * RP + 1;

    TiledScan S;
    for (int av = 0; av < Ac / 4; av++) {
        float4 v4 = src[av];
        int a = av * 4;
        dst[a + 0] = tscan_step(S, v4.x, a + 0);
        dst[a + 1] = tscan_step(S, v4.y, a + 1);
        dst[a + 2] = tscan_step(S, v4.z, a + 2);
        dst[a + 3] = tscan_step(S, v4.w, a + 3);
    }
}

// ---------------- K_border: zero row 0 / col 0 of both SATs -----------------
__global__ void k_border()
{
    int t = blockIdx.x * blockDim.x + threadIdx.x;
    int total = (Bc * Cc + Bc) * RP * 2;
    if (t >= total) return;
    int slice = t / (RP * 2);
    int rem   = t % (RP * 2);
    float* base = (slice < Bc * Cc)
        ? g_satc + (size_t)slice * RP * RP
        : g_sata + (size_t)(slice - Bc * Cc) * RP * RP;
    if (rem < RP) base[rem] = 0.f;
    else          base[(size_t)(rem - RP) * RP] = 0.f;
}

// ---------------- K3: per-detection vals, argmax, prb ------------------------
__global__ void __launch_bounds__(256) k_detect(
    const int* __restrict__ det_b, const int* __restrict__ det_c,
    const int* __restrict__ det_r, const int* __restrict__ det_a,
    const int* __restrict__ radus, const float* __restrict__ pred,
    float* __restrict__ out)
{
    const int g = blockIdx.x;
    const int t = threadIdx.x;

    __shared__ float v3[Kc][NS];
    __shared__ float se[NS];

    if (t < Kc * NS) {
        const int k  = t / NS;
        const int s  = t % NS;
        const int sh = s - 20;
        const int gk = g * Kc + k;
        const int dr = det_r[gk], da = det_a[gk], db = det_b[gk];
        const int dc = det_c[gk], rad = radus[gk];

        const int rc = dr + sh;
        const int r1 = min(max(rc - rad, 0), Rc);
        const int r2 = min(max(rc + rad + 1, 0), Rc);
        const int a1 = min(max(da - 2, 0), Ac);
        const int a2 = min(max(da + 3, 0), Ac);

        float xw = __fdiv_rn(-(float)(sh < 0 ? -sh : sh), 200.0f);
        float w  = (float)exp((double)xw);   // correctly-rounded f32 exp

        const float* sc = g_satc + ((size_t)(db * Cc + dc)) * RP * RP;
        const float* sa = g_sata + ((size_t)db) * RP * RP;

        float c22 = sc[(size_t)r2 * RP + a2], c12 = sc[(size_t)r1 * RP + a2];
        float c21 = sc[(size_t)r2 * RP + a1], c11 = sc[(size_t)r1 * RP + a1];
        float rect4 = __fadd_rn(__fsub_rn(__fsub_rn(c22, c12), c21), c11);
        float val1  = __fmul_rn(rect4, w);

        float d22 = sa[(size_t)r2 * RP + a2], d12 = sa[(size_t)r1 * RP + a2];
        float d21 = sa[(size_t)r2 * RP + a1], d11 = sa[(size_t)r1 * RP + a1];
        float rect3 = __fadd_rn(__fsub_rn(__fsub_rn(d22, d12), d21), d11);
        float val2  = __fmul_rn(rect3, w);

        float val3 = __fadd_rn(__fmul_rn(0.5f, val1),
                               __fmul_rn(0.5f, __fsub_rn(val2, val1)));
        v3[k][s] = val3;
    }
    __syncthreads();

    if (t < NS) {
        float s0 = __fadd_rn(__fadd_rn(__fadd_rn(v3[0][t], v3[1][t]), v3[2][t]), v3[3][t]);
        se[t] = s0;
        out[(size_t)g * NS + t] = s0;
    }
    __syncthreads();

    if (t == 0) {
        float best = se[0];
        int bi = 0;
        #pragma unroll
        for (int i = 1; i < NS; i++)
            if (se[i] > best) { best = se[i]; bi = i; }   // first occurrence
        const int shift = bi - 20;

        float pm = 0.3f;
        #pragma unroll
        for (int kk = 0; kk < Kc; kk++) {
            const int gg = g * Kc + kk;
            const int rr = min(max(det_r[gg] + shift, 0), Rc - 1);
            const int db = det_b[gg], da = det_a[gg];
            #pragma unroll
            for (int c = 0; c < Cc; c++)
                pm = fmaxf(pm, __ldg(pred + (((size_t)db * Cc + c) * Rc + rr) * Ac + da));
        }

        out[(size_t)Gc * NS       + g] = (float)shift;
        out[(size_t)Gc * (NS + 1) + g] = best;
        out[(size_t)Gc * (NS + 2) + g] = pm;
    }
}

extern "C" void kernel_launch(void* const* d_in, const int* in_sizes, int n_in,
                              void* d_out, int out_size)
{
    const float* pred  = (const float*)d_in[0];
    const int*   det_b = (const int*)  d_in[1];
    const int*   det_c = (const int*)  d_in[2];
    const int*   det_r = (const int*)  d_in[3];
    const int*   det_a = (const int*)  d_in[4];
    const int*   radus = (const int*)  d_in[5];
    float*       out   = (float*)d_out;

    k_rowscan<<<(Bc * Qc * Ac + 255) / 256, 256>>>(pred);
    k_colscan<<<(Bc * Qc * Rc + 255) / 256, 256>>>();
    int btot = (Bc * Cc + Bc) * RP * 2;
    k_border<<<(btot + 255) / 256, 256>>>();
    k_detect<<<Gc, 256>>>(det_b, det_c, det_r, det_a, radus, pred, out);
}

// round 5
// speedup vs baseline: 1.4450x; 1.4450x over previous
#include <cuda_runtime.h>
#include <math.h>

#define Bc   16
#define Cc   3
#define Rc   512
#define Ac   512
#define Gc   4096
#define Kc   4
#define NS   41     // shifts -20..+20
#define RP   513    // padded SAT dim
#define Qc   4      // 3 channels + channel-sum

// Static scratch
__device__ float g_y[(size_t)Bc * Qc * Rc * Ac];    // row-cumsum: q=0..2 channels, q=3 chan-sum
__device__ float g_satc[(size_t)Bc * Cc * RP * RP]; // padded per-channel SAT
__device__ float g_sata[(size_t)Bc * RP * RP];      // padded channel-sum SAT

// ---- XLA ReduceWindowRewriter (base_length=16) streaming scan state -------
// prefix(16t+j) = carry(t) + seq(x[16t..16t+j]);  tile totals scanned in two
// sequential halves of 16 with a single U0-combine for the upper half.
struct TiledScan {
    float acc_inner, carry, accT_low, accT_hi, U0;
};
__device__ __forceinline__ float tscan_step(TiledScan& S, float v, int r)
{
    const int j = r & 15;
    const int t = r >> 4;
    S.acc_inner = (j == 0) ? v : __fadd_rn(S.acc_inner, v);
    float out = (t == 0) ? S.acc_inner : __fadd_rn(S.carry, S.acc_inner);
    if (j == 15) {
        float T = S.acc_inner;
        float incT;
        if (t < 16) {
            S.accT_low = (t == 0) ? T : __fadd_rn(S.accT_low, T);
            incT = S.accT_low;
            if (t == 15) S.U0 = S.accT_low;
        } else {
            S.accT_hi = (t == 16) ? T : __fadd_rn(S.accT_hi, T);
            incT = __fadd_rn(S.U0, S.accT_hi);
        }
        S.carry = incT;
    }
    return out;
}

// ---------------- K1: row-axis scans (thread per (b,q,a)), coalesced --------
__global__ void __launch_bounds__(256) k_rowscan(const float* __restrict__ pred)
{
    int tid = blockIdx.x * blockDim.x + threadIdx.x;
    if (tid >= Bc * Qc * Ac) return;
    const int a  = tid & (Ac - 1);
    const int qb = tid >> 9;
    const int q  = qb & 3;
    const int b  = qb >> 2;

    const float* p = pred + ((size_t)b * Cc * Rc) * Ac + a;
    float* y = g_y + (((size_t)b * Qc + q) * Rc) * Ac + a;

    TiledScan S;
    for (int r = 0; r < Rc; r++) {
        float v;
        if (q < 3) {
            v = __ldg(p + ((size_t)q * Rc + r) * Ac);
        } else {
            float v0 = __ldg(p + (size_t)r * Ac);
            float v1 = __ldg(p + ((size_t)Rc + r) * Ac);
            float v2 = __ldg(p + ((size_t)2 * Rc + r) * Ac);
            v = __fadd_rn(__fadd_rn(v0, v1), v2);   // (p0+p1)+p2
        }
        y[(size_t)r * Ac] = tscan_step(S, v, r);
    }
}

// ---------------- K2: col-axis scans, WARP per row, identical add DAG -------
// lane t owns tile t (16 elems): sequential inner prefix; lane 0 folds the 32
// tile totals in the exact low/hi + U0-combine order; all lanes apply carry.
// Output staged via padded smem for fully-coalesced stores. Border zeros fused.
__global__ void __launch_bounds__(256) k_colscan()
{
    const int gwarp = (blockIdx.x * blockDim.x + threadIdx.x) >> 5;
    const int lane  = threadIdx.x & 31;
    const int wib   = threadIdx.x >> 5;

    __shared__ float s_tot[8][32];
    __shared__ float s_row[8][32 * 17];   // pad 17: conflict-free staging

    const int r  = gwarp & (Rc - 1);
    const int qb = gwarp >> 9;
    const int q  = qb & 3;
    const int b  = qb >> 2;

    const float4* src = (const float4*)(g_y + (((size_t)b * Qc + q) * Rc + r) * Ac);
    float* dstbase = (q < 3)
        ? g_satc + ((size_t)(b * Cc + q)) * RP * RP
        : g_sata + ((size_t)b) * RP * RP;
    float* dst = dstbase + (size_t)(r + 1) * RP;   // this SAT row (col 0 = pad)

    // load tile (16 floats) for lane
    float px[16];
    {
        float4 v0 = src[lane * 4 + 0];
        float4 v1 = src[lane * 4 + 1];
        float4 v2 = src[lane * 4 + 2];
        float4 v3 = src[lane * 4 + 3];
        px[0]=v0.x; px[1]=v0.y; px[2]=v0.z; px[3]=v0.w;
        px[4]=v1.x; px[5]=v1.y; px[6]=v1.z; px[7]=v1.w;
        px[8]=v2.x; px[9]=v2.y; px[10]=v2.z; px[11]=v2.w;
        px[12]=v3.x; px[13]=v3.y; px[14]=v3.z; px[15]=v3.w;
    }
    // inner sequential prefix (exact acc_inner order)
    #pragma unroll
    for (int j = 1; j < 16; j++) px[j] = __fadd_rn(px[j-1], px[j]);

    s_tot[wib][lane] = px[15];
    __syncwarp();

    if (lane == 0) {
        // sequential totals scan, in-place carry writeback (scalars only)
        float acc = s_tot[wib][0];                 // incT[0]
        #pragma unroll
        for (int t2 = 1; t2 < 16; t2++) {
            float T = s_tot[wib][t2];
            s_tot[wib][t2] = acc;                  // carry[t2] = incT[t2-1]
            acc = __fadd_rn(acc, T);               // incT[t2]
        }
        float U0 = acc;                            // fold of T[0..15]
        float T16 = s_tot[wib][16];
        s_tot[wib][16] = acc;                      // carry[16] = incT[15]
        float acch = T16;
        acc = __fadd_rn(U0, acch);                 // incT[16]
        #pragma unroll
        for (int t2 = 17; t2 < 32; t2++) {
            float T = s_tot[wib][t2];
            s_tot[wib][t2] = acc;                  // carry[t2] = incT[t2-1]
            acch = __fadd_rn(acch, T);
            acc = __fadd_rn(U0, acch);             // incT[t2]
        }
    }
    __syncwarp();

    const float carry = s_tot[wib][lane];
    #pragma unroll
    for (int j = 0; j < 16; j++) {
        float o = (lane == 0) ? px[j] : __fadd_rn(carry, px[j]);
        s_row[wib][lane * 17 + j] = o;
    }
    __syncwarp();

    // coalesced store of the 512 scanned values (+ col-0 zero)
    #pragma unroll
    for (int i = 0; i < 16; i++) {
        int m = i * 32 + lane;
        dst[1 + m] = s_row[wib][(m >> 4) * 17 + (m & 15)];
    }
    if (lane == 0) dst[0] = 0.f;
    if (r == 0) {                                   // fused border: SAT row 0
        for (int i = lane; i < RP; i += 32) dstbase[i] = 0.f;
    }
}

// ---------------- K3: per-detection vals, argmax, prb ------------------------
__global__ void __launch_bounds__(192) k_detect(
    const int* __restrict__ det_b, const int* __restrict__ det_c,
    const int* __restrict__ det_r, const int* __restrict__ det_a,
    const int* __restrict__ radus, const float* __restrict__ pred,
    float* __restrict__ out)
{
    const int g = blockIdx.x;
    const int t = threadIdx.x;

    __shared__ float v3[Kc][NS];
    __shared__ float se[NS];

    if (t < Kc * NS) {
        const int k  = t / NS;
        const int s  = t % NS;
        const int sh = s - 20;
        const int gk = g * Kc + k;
        const int dr = det_r[gk], da = det_a[gk], db = det_b[gk];
        const int dc = det_c[gk], rad = radus[gk];

        const int rc = dr + sh;
        const int r1 = min(max(rc - rad, 0), Rc);
        const int r2 = min(max(rc + rad + 1, 0), Rc);
        const int a1 = min(max(da - 2, 0), Ac);
        const int a2 = min(max(da + 3, 0), Ac);

        float xw = __fdiv_rn(-(float)(sh < 0 ? -sh : sh), 200.0f);
        float w  = (float)exp((double)xw);   // correctly-rounded f32 exp

        const float* sc = g_satc + ((size_t)(db * Cc + dc)) * RP * RP;
        const float* sa = g_sata + ((size_t)db) * RP * RP;

        float c22 = sc[(size_t)r2 * RP + a2], c12 = sc[(size_t)r1 * RP + a2];
        float c21 = sc[(size_t)r2 * RP + a1], c11 = sc[(size_t)r1 * RP + a1];
        float rect4 = __fadd_rn(__fsub_rn(__fsub_rn(c22, c12), c21), c11);
        float val1  = __fmul_rn(rect4, w);

        float d22 = sa[(size_t)r2 * RP + a2], d12 = sa[(size_t)r1 * RP + a2];
        float d21 = sa[(size_t)r2 * RP + a1], d11 = sa[(size_t)r1 * RP + a1];
        float rect3 = __fadd_rn(__fsub_rn(__fsub_rn(d22, d12), d21), d11);
        float val2  = __fmul_rn(rect3, w);

        float val3 = __fadd_rn(__fmul_rn(0.5f, val1),
                               __fmul_rn(0.5f, __fsub_rn(val2, val1)));
        v3[k][s] = val3;
    }
    __syncthreads();

    if (t < NS) {
        float s0 = __fadd_rn(__fadd_rn(__fadd_rn(v3[0][t], v3[1][t]), v3[2][t]), v3[3][t]);
        se[t] = s0;
        out[(size_t)g * NS + t] = s0;
    }
    __syncthreads();

    if (t == 0) {
        float best = se[0];
        int bi = 0;
        #pragma unroll
        for (int i = 1; i < NS; i++)
            if (se[i] > best) { best = se[i]; bi = i; }   // first occurrence
        const int shift = bi - 20;

        float pm = 0.3f;
        #pragma unroll
        for (int kk = 0; kk < Kc; kk++) {
            const int gg = g * Kc + kk;
            const int rr = min(max(det_r[gg] + shift, 0), Rc - 1);
            const int db = det_b[gg], da = det_a[gg];
            #pragma unroll
            for (int c = 0; c < Cc; c++)
                pm = fmaxf(pm, __ldg(pred + (((size_t)db * Cc + c) * Rc + rr) * Ac + da));
        }

        out[(size_t)Gc * NS       + g] = (float)shift;
        out[(size_t)Gc * (NS + 1) + g] = best;
        out[(size_t)Gc * (NS + 2) + g] = pm;
    }
}

extern "C" void kernel_launch(void* const* d_in, const int* in_sizes, int n_in,
                              void* d_out, int out_size)
{
    const float* pred  = (const float*)d_in[0];
    const int*   det_b = (const int*)  d_in[1];
    const int*   det_c = (const int*)  d_in[2];
    const int*   det_r = (const int*)  d_in[3];
    const int*   det_a = (const int*)  d_in[4];
    const int*   radus = (const int*)  d_in[5];
    float*       out   = (float*)d_out;

    k_rowscan<<<(Bc * Qc * Ac + 255) / 256, 256>>>(pred);
    k_colscan<<<(Bc * Qc * Rc * 32 + 255) / 256, 256>>>();   // warp per SAT row
    k_detect<<<Gc, 192>>>(det_b, det_c, det_r, det_a, radus, pred, out);
}

// round 6
// speedup vs baseline: 3.2000x; 2.2145x over previous
#include <cuda_runtime.h>
#include <math.h>

#define Bc   16
#define Cc   3
#define Rc   512
#define Ac   512
#define Gc   4096
#define Kc   4
#define NS   41     // shifts -20..+20
#define RP   513    // padded SAT dim
#define Qc   4      // 3 channels + channel-sum

// Static scratch
__device__ float g_y[(size_t)Bc * Qc * Rc * Ac];    // row-cumsum: q=0..2 channels, q=3 chan-sum
__device__ float g_satc[(size_t)Bc * Cc * RP * RP]; // padded per-channel SAT
__device__ float g_sata[(size_t)Bc * RP * RP];      // padded channel-sum SAT

// ---------------- K1: row-axis scans, tile-parallel (warp-coalesced) --------
// XLA ReduceWindowRewriter(base=16) DAG: tile t = rows 16t..16t+15 inner
// sequential prefix; 32 tile totals folded serially (low half, U0, high half);
// out = carry(t) + inner. Thread (t, tx): tile t, column a = 32*acol + tx.
__global__ void __launch_bounds__(1024) k_rowscan(const float* __restrict__ pred)
{
    const int blk  = blockIdx.x;          // 0..1023
    const int acol = blk & 15;
    const int q    = (blk >> 4) & 3;
    const int b    = blk >> 6;
    const int tx   = threadIdx.x & 31;
    const int t    = threadIdx.x >> 5;    // tile 0..31
    const int a    = acol * 32 + tx;

    __shared__ float s_tot[32][33];

    const float* p = pred + ((size_t)b * Cc * Rc) * Ac + a;

    float px[16];
    if (q < 3) {
        const float* pc = p + ((size_t)q * Rc + (size_t)t * 16) * Ac;
        #pragma unroll
        for (int j = 0; j < 16; j++) px[j] = __ldg(pc + (size_t)j * Ac);
    } else {
        #pragma unroll
        for (int j = 0; j < 16; j++) {
            const int r = t * 16 + j;
            float v0 = __ldg(p + (size_t)r * Ac);
            float v1 = __ldg(p + ((size_t)Rc + r) * Ac);
            float v2 = __ldg(p + ((size_t)2 * Rc + r) * Ac);
            px[j] = __fadd_rn(__fadd_rn(v0, v1), v2);   // (p0+p1)+p2
        }
    }
    // inner sequential prefix (exact acc_inner order)
    #pragma unroll
    for (int j = 1; j < 16; j++) px[j] = __fadd_rn(px[j-1], px[j]);

    s_tot[t][tx] = px[15];
    __syncthreads();

    if (t == 0) {   // warp 0: thread tx folds column a's 32 totals, exact order
        float acc = s_tot[0][tx];                    // incT[0]
        #pragma unroll
        for (int t2 = 1; t2 < 16; t2++) {
            float T = s_tot[t2][tx];
            s_tot[t2][tx] = acc;                     // carry[t2] = incT[t2-1]
            acc = __fadd_rn(acc, T);
        }
        float U0  = acc;                             // fold of T[0..15]
        float T16 = s_tot[16][tx];
        s_tot[16][tx] = acc;                         // carry[16] = incT[15]
        float acch = T16;
        acc = __fadd_rn(U0, acch);                   // incT[16]
        #pragma unroll
        for (int t2 = 17; t2 < 32; t2++) {
            float T = s_tot[t2][tx];
            s_tot[t2][tx] = acc;                     // carry[t2] = incT[t2-1]
            acch = __fadd_rn(acch, T);
            acc = __fadd_rn(U0, acch);
        }
    }
    __syncthreads();

    const float carry = s_tot[t][tx];                // t==0: unused
    float* y = g_y + (((size_t)b * Qc + q) * Rc + (size_t)t * 16) * Ac + a;
    #pragma unroll
    for (int j = 0; j < 16; j++) {
        float o = (t == 0) ? px[j] : __fadd_rn(carry, px[j]);
        y[(size_t)j * Ac] = o;
    }
}

// ---------------- K2: col-axis scans, WARP per row, identical add DAG -------
__global__ void __launch_bounds__(256) k_colscan()
{
    const int gwarp = (blockIdx.x * blockDim.x + threadIdx.x) >> 5;
    const int lane  = threadIdx.x & 31;
    const int wib   = threadIdx.x >> 5;

    __shared__ float s_tot[8][32];
    __shared__ float s_row[8][32 * 17];   // pad 17: conflict-free staging

    const int r  = gwarp & (Rc - 1);
    const int qb = gwarp >> 9;
    const int q  = qb & 3;
    const int b  = qb >> 2;

    const float4* src = (const float4*)(g_y + (((size_t)b * Qc + q) * Rc + r) * Ac);
    float* dstbase = (q < 3)
        ? g_satc + ((size_t)(b * Cc + q)) * RP * RP
        : g_sata + ((size_t)b) * RP * RP;
    float* dst = dstbase + (size_t)(r + 1) * RP;

    float px[16];
    {
        float4 v0 = src[lane * 4 + 0];
        float4 v1 = src[lane * 4 + 1];
        float4 v2 = src[lane * 4 + 2];
        float4 v3 = src[lane * 4 + 3];
        px[0]=v0.x; px[1]=v0.y; px[2]=v0.z; px[3]=v0.w;
        px[4]=v1.x; px[5]=v1.y; px[6]=v1.z; px[7]=v1.w;
        px[8]=v2.x; px[9]=v2.y; px[10]=v2.z; px[11]=v2.w;
        px[12]=v3.x; px[13]=v3.y; px[14]=v3.z; px[15]=v3.w;
    }
    #pragma unroll
    for (int j = 1; j < 16; j++) px[j] = __fadd_rn(px[j-1], px[j]);

    s_tot[wib][lane] = px[15];
    __syncwarp();

    if (lane == 0) {
        float acc = s_tot[wib][0];
        #pragma unroll
        for (int t2 = 1; t2 < 16; t2++) {
            float T = s_tot[wib][t2];
            s_tot[wib][t2] = acc;
            acc = __fadd_rn(acc, T);
        }
        float U0 = acc;
        float T16 = s_tot[wib][16];
        s_tot[wib][16] = acc;
        float acch = T16;
        acc = __fadd_rn(U0, acch);
        #pragma unroll
        for (int t2 = 17; t2 < 32; t2++) {
            float T = s_tot[wib][t2];
            s_tot[wib][t2] = acc;
            acch = __fadd_rn(acch, T);
            acc = __fadd_rn(U0, acch);
        }
    }
    __syncwarp();

    const float carry = s_tot[wib][lane];
    #pragma unroll
    for (int j = 0; j < 16; j++) {
        float o = (lane == 0) ? px[j] : __fadd_rn(carry, px[j]);
        s_row[wib][lane * 17 + j] = o;
    }
    __syncwarp();

    #pragma unroll
    for (int i = 0; i < 16; i++) {
        int m = i * 32 + lane;
        dst[1 + m] = s_row[wib][(m >> 4) * 17 + (m & 15)];
    }
    if (lane == 0) dst[0] = 0.f;
    if (r == 0) {
        for (int i = lane; i < RP; i += 32) dstbase[i] = 0.f;
    }
}

// ---------------- K3: per-detection vals, argmax, prb ------------------------
__global__ void __launch_bounds__(192) k_detect(
    const int* __restrict__ det_b, const int* __restrict__ det_c,
    const int* __restrict__ det_r, const int* __restrict__ det_a,
    const int* __restrict__ radus, const float* __restrict__ pred,
    float* __restrict__ out)
{
    const int g = blockIdx.x;
    const int t = threadIdx.x;

    __shared__ float v3[Kc][NS];
    __shared__ float se[NS];

    if (t < Kc * NS) {
        const int k  = t / NS;
        const int s  = t % NS;
        const int sh = s - 20;
        const int gk = g * Kc + k;
        const int dr = det_r[gk], da = det_a[gk], db = det_b[gk];
        const int dc = det_c[gk], rad = radus[gk];

        const int rc = dr + sh;
        const int r1 = min(max(rc - rad, 0), Rc);
        const int r2 = min(max(rc + rad + 1, 0), Rc);
        const int a1 = min(max(da - 2, 0), Ac);
        const int a2 = min(max(da + 3, 0), Ac);

        float xw = __fdiv_rn(-(float)(sh < 0 ? -sh : sh), 200.0f);
        float w  = (float)exp((double)xw);   // correctly-rounded f32 exp

        const float* sc = g_satc + ((size_t)(db * Cc + dc)) * RP * RP;
        const float* sa = g_sata + ((size_t)db) * RP * RP;

        float c22 = sc[(size_t)r2 * RP + a2], c12 = sc[(size_t)r1 * RP + a2];
        float c21 = sc[(size_t)r2 * RP + a1], c11 = sc[(size_t)r1 * RP + a1];
        float rect4 = __fadd_rn(__fsub_rn(__fsub_rn(c22, c12), c21), c11);
        float val1  = __fmul_rn(rect4, w);

        float d22 = sa[(size_t)r2 * RP + a2], d12 = sa[(size_t)r1 * RP + a2];
        float d21 = sa[(size_t)r2 * RP + a1], d11 = sa[(size_t)r1 * RP + a1];
        float rect3 = __fadd_rn(__fsub_rn(__fsub_rn(d22, d12), d21), d11);
        float val2  = __fmul_rn(rect3, w);

        float val3 = __fadd_rn(__fmul_rn(0.5f, val1),
                               __fmul_rn(0.5f, __fsub_rn(val2, val1)));
        v3[k][s] = val3;
    }
    __syncthreads();

    if (t < NS) {
        float s0 = __fadd_rn(__fadd_rn(__fadd_rn(v3[0][t], v3[1][t]), v3[2][t]), v3[3][t]);
        se[t] = s0;
        out[(size_t)g * NS + t] = s0;
    }
    __syncthreads();

    if (t == 0) {
        float best = se[0];
        int bi = 0;
        #pragma unroll
        for (int i = 1; i < NS; i++)
            if (se[i] > best) { best = se[i]; bi = i; }   // first occurrence
        const int shift = bi - 20;

        float pm = 0.3f;
        #pragma unroll
        for (int kk = 0; kk < Kc; kk++) {
            const int gg = g * Kc + kk;
            const int rr = min(max(det_r[gg] + shift, 0), Rc - 1);
            const int db = det_b[gg], da = det_a[gg];
            #pragma unroll
            for (int c = 0; c < Cc; c++)
                pm = fmaxf(pm, __ldg(pred + (((size_t)db * Cc + c) * Rc + rr) * Ac + da));
        }

        out[(size_t)Gc * NS       + g] = (float)shift;
        out[(size_t)Gc * (NS + 1) + g] = best;
        out[(size_t)Gc * (NS + 2) + g] = pm;
    }
}

extern "C" void kernel_launch(void* const* d_in, const int* in_sizes, int n_in,
                              void* d_out, int out_size)
{
    const float* pred  = (const float*)d_in[0];
    const int*   det_b = (const int*)  d_in[1];
    const int*   det_c = (const int*)  d_in[2];
    const int*   det_r = (const int*)  d_in[3];
    const int*   det_a = (const int*)  d_in[4];
    const int*   radus = (const int*)  d_in[5];
    float*       out   = (float*)d_out;

    k_rowscan<<<Bc * Qc * (Ac / 32), 1024>>>(pred);           // 1024 blocks
    k_colscan<<<(Bc * Qc * Rc * 32 + 255) / 256, 256>>>();    // warp per SAT row
    k_detect<<<Gc, 192>>>(det_b, det_c, det_r, det_a, radus, pred, out);
}

// round 7
// speedup vs baseline: 3.2653x; 1.0204x over previous
#include <cuda_runtime.h>
#include <math.h>

#define Bc   16
#define Cc   3
#define Rc   512
#define Ac   512
#define Gc   4096
#define Kc   4
#define NS   41     // shifts -20..+20
#define Qc   4      // 3 channels + channel-sum

// Transposed SAT layout: value SAT[r][a] stored at slice[BOFF + a*RPT + r]
#define RPT  544                 // padded row stride (a-major), 32-aligned
#define BOFF 31                  // base offset so (r+1+BOFF) is 32-aligned at ty=0
#define SST  (513 * RPT + 64)    // slice stride (elements), 32-aligned

// Static scratch
__device__ float g_y[(size_t)Bc * Qc * Rc * Ac];    // row-cumsum: q=0..2 channels, q=3 chan-sum
__device__ float g_satc[(size_t)Bc * Cc * SST];     // transposed per-channel SAT
__device__ float g_sata[(size_t)Bc * SST];          // transposed channel-sum SAT

// ---------------- K1: row-axis scans, tile-parallel (warp-coalesced) --------
// XLA ReduceWindowRewriter(base=16) DAG: tile t = rows 16t..16t+15 inner
// sequential prefix; 32 tile totals folded serially (low half, U0, high half);
// out = carry(t) + inner.
__global__ void __launch_bounds__(1024) k_rowscan(const float* __restrict__ pred)
{
    const int blk  = blockIdx.x;          // 0..1023
    const int acol = blk & 15;
    const int q    = (blk >> 4) & 3;
    const int b    = blk >> 6;
    const int tx   = threadIdx.x & 31;
    const int t    = threadIdx.x >> 5;    // tile 0..31
    const int a    = acol * 32 + tx;

    __shared__ float s_tot[32][33];

    const float* p = pred + ((size_t)b * Cc * Rc) * Ac + a;

    float px[16];
    if (q < 3) {
        const float* pc = p + ((size_t)q * Rc + (size_t)t * 16) * Ac;
        #pragma unroll
        for (int j = 0; j < 16; j++) px[j] = __ldg(pc + (size_t)j * Ac);
    } else {
        #pragma unroll
        for (int j = 0; j < 16; j++) {
            const int r = t * 16 + j;
            float v0 = __ldg(p + (size_t)r * Ac);
            float v1 = __ldg(p + ((size_t)Rc + r) * Ac);
            float v2 = __ldg(p + ((size_t)2 * Rc + r) * Ac);
            px[j] = __fadd_rn(__fadd_rn(v0, v1), v2);   // (p0+p1)+p2
        }
    }
    #pragma unroll
    for (int j = 1; j < 16; j++) px[j] = __fadd_rn(px[j-1], px[j]);

    s_tot[t][tx] = px[15];
    __syncthreads();

    if (t == 0) {
        float acc = s_tot[0][tx];
        #pragma unroll
        for (int t2 = 1; t2 < 16; t2++) {
            float T = s_tot[t2][tx];
            s_tot[t2][tx] = acc;
            acc = __fadd_rn(acc, T);
        }
        float U0  = acc;
        float T16 = s_tot[16][tx];
        s_tot[16][tx] = acc;
        float acch = T16;
        acc = __fadd_rn(U0, acch);
        #pragma unroll
        for (int t2 = 17; t2 < 32; t2++) {
            float T = s_tot[t2][tx];
            s_tot[t2][tx] = acc;
            acch = __fadd_rn(acch, T);
            acc = __fadd_rn(U0, acch);
        }
    }
    __syncthreads();

    const float carry = s_tot[t][tx];
    float* y = g_y + (((size_t)b * Qc + q) * Rc + (size_t)t * 16) * Ac + a;
    #pragma unroll
    for (int j = 0; j < 16; j++) {
        float o = (t == 0) ? px[j] : __fadd_rn(carry, px[j]);
        y[(size_t)j * Ac] = o;
    }
}

// ---------------- K2: col-axis scans -> TRANSPOSED SAT ----------------------
// Block = 512 threads: 16-row stripe of one (b,q). Thread (t,ty): a-tile t
// (16 cols) of stripe row ty. Identical scan DAG per row; output written
// a-major (sat_T[a][r]) with r contiguous across ty-lanes -> coalesced.
__global__ void __launch_bounds__(512) k_colscan()
{
    const int blk  = blockIdx.x;           // (b,q,rblk): 16*4*32
    const int rblk = blk & 31;
    const int q    = (blk >> 5) & 3;
    const int b    = blk >> 7;
    const int tid  = threadIdx.x;
    const int ty   = tid & 15;              // row in stripe
    const int t    = tid >> 4;              // a-tile 0..31

    __shared__ float s_in[16][545];         // map(m)=m+(m>>4)=17t+j, stride 545
    __shared__ float s_tot[16][33];

    const float* src = g_y + (((size_t)b * Qc + q) * Rc + (size_t)rblk * 16) * Ac;

    // phase 1: coalesced stripe load (16x512)
    #pragma unroll
    for (int i = 0; i < 16; i++) {
        int idx = i * 512 + tid;
        int rr = idx >> 9, cc = idx & 511;
        s_in[rr][cc + (cc >> 4)] = src[(size_t)rr * Ac + cc];
    }
    __syncthreads();

    // phase 2: inner sequential prefix along a (exact acc_inner order)
    float px[16];
    #pragma unroll
    for (int j = 0; j < 16; j++) px[j] = s_in[ty][17 * t + j];
    #pragma unroll
    for (int j = 1; j < 16; j++) px[j] = __fadd_rn(px[j-1], px[j]);
    s_tot[ty][t] = px[15];
    __syncthreads();

    // phase 3: totals fold per row (exact low/U0/high order)
    if (t == 0) {
        float acc = s_tot[ty][0];
        #pragma unroll
        for (int t2 = 1; t2 < 16; t2++) {
            float T = s_tot[ty][t2];
            s_tot[ty][t2] = acc;
            acc = __fadd_rn(acc, T);
        }
        float U0  = acc;
        float T16 = s_tot[ty][16];
        s_tot[ty][16] = acc;
        float acch = T16;
        acc = __fadd_rn(U0, acch);
        #pragma unroll
        for (int t2 = 17; t2 < 32; t2++) {
            float T = s_tot[ty][t2];
            s_tot[ty][t2] = acc;
            acch = __fadd_rn(acch, T);
            acc = __fadd_rn(U0, acch);
        }
    }
    __syncthreads();

    const float carry = s_tot[ty][t];
    float* dstb = (q < 3)
        ? g_satc + (size_t)(b * Cc + q) * SST + BOFF
        : g_sata + (size_t)b * SST + BOFF;
    const int r = rblk * 16 + ty;

    #pragma unroll
    for (int j = 0; j < 16; j++) {
        float o = (t == 0) ? px[j] : __fadd_rn(carry, px[j]);
        int a = t * 16 + j;
        dstb[(size_t)(a + 1) * RPT + (r + 1)] = o;   // sat_T[a+1][r+1]
    }

    if (rblk == 0) {   // fused borders: sat_T[0][*] and sat_T[*][0]
        for (int i = tid; i < 513; i += 512) {
            dstb[i] = 0.f;                     // a = 0 plane (contiguous in r)
            dstb[(size_t)i * RPT] = 0.f;       // r = 0 plane
        }
    }
}

// ---------------- K3: per-detection vals, argmax, prb (transposed SAT) ------
__global__ void __launch_bounds__(192) k_detect(
    const int* __restrict__ det_b, const int* __restrict__ det_c,
    const int* __restrict__ det_r, const int* __restrict__ det_a,
    const int* __restrict__ radus, const float* __restrict__ pred,
    float* __restrict__ out)
{
    const int g = blockIdx.x;
    const int t = threadIdx.x;

    __shared__ float v3[Kc][NS];
    __shared__ float se[NS];
    __shared__ int   s_shift;
    __shared__ float s_pm[12];

    if (t < Kc * NS) {
        const int k  = t / NS;
        const int s  = t % NS;
        const int sh = s - 20;
        const int gk = g * Kc + k;
        const int dr = det_r[gk], da = det_a[gk], db = det_b[gk];
        const int dc = det_c[gk], rad = radus[gk];

        const int rc = dr + sh;
        const int r1 = min(max(rc - rad, 0), Rc);
        const int r2 = min(max(rc + rad + 1, 0), Rc);
        const int a1 = min(max(da - 2, 0), Ac);
        const int a2 = min(max(da + 3, 0), Ac);

        float xw = __fdiv_rn(-(float)(sh < 0 ? -sh : sh), 200.0f);
        float w  = (float)exp((double)xw);   // correctly-rounded f32 exp

        const float* sc = g_satc + (size_t)(db * Cc + dc) * SST + BOFF;
        const float* sa = g_sata + (size_t)db * SST + BOFF;

        // transposed: SAT[r][a] == slice[a*RPT + r]; lanes (consecutive s) hit
        // consecutive r -> coalesced
        float c22 = sc[(size_t)a2 * RPT + r2], c12 = sc[(size_t)a2 * RPT + r1];
        float c21 = sc[(size_t)a1 * RPT + r2], c11 = sc[(size_t)a1 * RPT + r1];
        float rect4 = __fadd_rn(__fsub_rn(__fsub_rn(c22, c12), c21), c11);
        float val1  = __fmul_rn(rect4, w);

        float d22 = sa[(size_t)a2 * RPT + r2], d12 = sa[(size_t)a2 * RPT + r1];
        float d21 = sa[(size_t)a1 * RPT + r2], d11 = sa[(size_t)a1 * RPT + r1];
        float rect3 = __fadd_rn(__fsub_rn(__fsub_rn(d22, d12), d21), d11);
        float val2  = __fmul_rn(rect3, w);

        float val3 = __fadd_rn(__fmul_rn(0.5f, val1),
                               __fmul_rn(0.5f, __fsub_rn(val2, val1)));
        v3[k][s] = val3;
    }
    __syncthreads();

    if (t < NS) {
        float s0 = __fadd_rn(__fadd_rn(__fadd_rn(v3[0][t], v3[1][t]), v3[2][t]), v3[3][t]);
        se[t] = s0;
        out[(size_t)g * NS + t] = s0;
    }
    __syncthreads();

    if (t == 0) {
        float best = se[0];
        int bi = 0;
        #pragma unroll
        for (int i = 1; i < NS; i++)
            if (se[i] > best) { best = se[i]; bi = i; }   // first occurrence
        s_shift = bi - 20;
        out[(size_t)Gc * NS       + g] = (float)(bi - 20);
        out[(size_t)Gc * (NS + 1) + g] = best;
    }
    __syncthreads();

    if (t < 12) {   // parallel prb_max gather: kk = t/3, c = t%3
        const int kk = t / 3, c = t % 3;
        const int gg = g * Kc + kk;
        const int rr = min(max(det_r[gg] + s_shift, 0), Rc - 1);
        const int db = det_b[gg], da = det_a[gg];
        s_pm[t] = __ldg(pred + (((size_t)db * Cc + c) * Rc + rr) * Ac + da);
    }
    __syncthreads();

    if (t == 0) {
        float pm = 0.3f;   // SMALL_PROB
        #pragma unroll
        for (int i = 0; i < 12; i++) pm = fmaxf(pm, s_pm[i]);
        out[(size_t)Gc * (NS + 2) + g] = pm;
    }
}

extern "C" void kernel_launch(void* const* d_in, const int* in_sizes, int n_in,
                              void* d_out, int out_size)
{
    const float* pred  = (const float*)d_in[0];
    const int*   det_b = (const int*)  d_in[1];
    const int*   det_c = (const int*)  d_in[2];
    const int*   det_r = (const int*)  d_in[3];
    const int*   det_a = (const int*)  d_in[4];
    const int*   radus = (const int*)  d_in[5];
    float*       out   = (float*)d_out;

    k_rowscan<<<Bc * Qc * (Ac / 32), 1024>>>(pred);   // 1024 blocks
    k_colscan<<<Bc * Qc * 32, 512>>>();               // 16-row stripes
    k_detect<<<Gc, 192>>>(det_b, det_c, det_r, det_a, radus, pred, out);
}

// round 8
// speedup vs baseline: 3.3347x; 1.0213x over previous
#include <cuda_runtime.h>
#include <math.h>

#define Bc   16
#define Cc   3
#define Rc   512
#define Ac   512
#define Gc   4096
#define Kc   4
#define NS   41     // shifts -20..+20
#define Qc   4      // 3 channels + channel-sum

// Transposed SAT layout: value SAT[r][a] stored at slice[BOFF + a*RPT + r]
#define RPT  544                 // padded row stride (a-major), 32-aligned
#define BOFF 31                  // base offset so (r+1+BOFF) is 32-aligned
#define SST  (513 * RPT + 64)    // slice stride (elements), 32-aligned

// Static scratch
__device__ float g_y[(size_t)Bc * Qc * Rc * Ac];    // row-cumsum: q=0..2 channels, q=3 chan-sum
__device__ float g_satc[(size_t)Bc * Cc * SST];     // transposed per-channel SAT
__device__ float g_sata[(size_t)Bc * SST];          // transposed channel-sum SAT

// ---- one XLA ReduceWindowRewriter(base=16) scan over 512 elems, in-block ---
// px[16] = this thread's tile (tile index t); totals folded serially per
// column tx by warp 0 in the exact low-half / U0 / high-half order.
__device__ __forceinline__ void scan_block(float (&px)[16], float* dst,
                                           int t, int tx, float (*s_tot)[33])
{
    #pragma unroll
    for (int j = 1; j < 16; j++) px[j] = __fadd_rn(px[j-1], px[j]);
    s_tot[t][tx] = px[15];
    __syncthreads();

    if (t == 0) {
        float acc = s_tot[0][tx];                    // incT[0]
        #pragma unroll
        for (int t2 = 1; t2 < 16; t2++) {
            float T = s_tot[t2][tx];
            s_tot[t2][tx] = acc;                     // carry[t2] = incT[t2-1]
            acc = __fadd_rn(acc, T);
        }
        float U0  = acc;                             // fold of T[0..15]
        float T16 = s_tot[16][tx];
        s_tot[16][tx] = acc;                         // carry[16] = incT[15]
        float acch = T16;
        acc = __fadd_rn(U0, acch);                   // incT[16]
        #pragma unroll
        for (int t2 = 17; t2 < 32; t2++) {
            float T = s_tot[t2][tx];
            s_tot[t2][tx] = acc;                     // carry[t2] = incT[t2-1]
            acch = __fadd_rn(acch, T);
            acc = __fadd_rn(U0, acch);
        }
    }
    __syncthreads();

    const float carry = s_tot[t][tx];
    #pragma unroll
    for (int j = 0; j < 16; j++) {
        float o = (t == 0) ? px[j] : __fadd_rn(carry, px[j]);
        dst[(size_t)j * Ac] = o;
    }
    __syncthreads();   // s_tot reused by next scan
}

// ---------------- K1: fused row-axis scans — single pred read ---------------
// Block = (b, 32-col stripe); produces ch0, ch1, ch2 and channel-sum scans.
__global__ void __launch_bounds__(1024) k_rowscan(const float* __restrict__ pred)
{
    const int blk  = blockIdx.x;          // 0..255
    const int acol = blk & 15;
    const int b    = blk >> 4;
    const int tx   = threadIdx.x & 31;
    const int t    = threadIdx.x >> 5;    // tile 0..31
    const int a    = acol * 32 + tx;

    __shared__ float s_tot[32][33];

    const float* p  = pred + ((size_t)b * Cc * Rc) * Ac + a;
    float*       yb = g_y  + ((size_t)b * Qc * Rc) * Ac + a;

    float ps[16];   // running channel sum (raw), exact (v0+v1)+v2 order

    #pragma unroll
    for (int c = 0; c < 3; c++) {
        float px[16];
        const float* pc = p + ((size_t)c * Rc + (size_t)t * 16) * Ac;
        #pragma unroll
        for (int j = 0; j < 16; j++) px[j] = __ldg(pc + (size_t)j * Ac);
        #pragma unroll
        for (int j = 0; j < 16; j++)
            ps[j] = (c == 0) ? px[j] : __fadd_rn(ps[j], px[j]);
        scan_block(px, yb + ((size_t)c * Rc + (size_t)t * 16) * Ac, t, tx, s_tot);
    }
    scan_block(ps, yb + ((size_t)3 * Rc + (size_t)t * 16) * Ac, t, tx, s_tot);
}

// ---------------- K2: col-axis scans -> TRANSPOSED SAT ----------------------
__global__ void __launch_bounds__(512) k_colscan()
{
    const int blk  = blockIdx.x;           // (b,q,rblk): 16*4*32
    const int rblk = blk & 31;
    const int q    = (blk >> 5) & 3;
    const int b    = blk >> 7;
    const int tid  = threadIdx.x;
    const int ty   = tid & 15;              // row in stripe
    const int t    = tid >> 4;              // a-tile 0..31

    __shared__ float s_in[16][545];
    __shared__ float s_tot[16][33];

    const float* src = g_y + (((size_t)b * Qc + q) * Rc + (size_t)rblk * 16) * Ac;

    #pragma unroll
    for (int i = 0; i < 16; i++) {
        int idx = i * 512 + tid;
        int rr = idx >> 9, cc = idx & 511;
        s_in[rr][cc + (cc >> 4)] = src[(size_t)rr * Ac + cc];
    }
    __syncthreads();

    float px[16];
    #pragma unroll
    for (int j = 0; j < 16; j++) px[j] = s_in[ty][17 * t + j];
    #pragma unroll
    for (int j = 1; j < 16; j++) px[j] = __fadd_rn(px[j-1], px[j]);
    s_tot[ty][t] = px[15];
    __syncthreads();

    if (t == 0) {
        float acc = s_tot[ty][0];
        #pragma unroll
        for (int t2 = 1; t2 < 16; t2++) {
            float T = s_tot[ty][t2];
            s_tot[ty][t2] = acc;
            acc = __fadd_rn(acc, T);
        }
        float U0  = acc;
        float T16 = s_tot[ty][16];
        s_tot[ty][16] = acc;
        float acch = T16;
        acc = __fadd_rn(U0, acch);
        #pragma unroll
        for (int t2 = 17; t2 < 32; t2++) {
            float T = s_tot[ty][t2];
            s_tot[ty][t2] = acc;
            acch = __fadd_rn(acch, T);
            acc = __fadd_rn(U0, acch);
        }
    }
    __syncthreads();

    const float carry = s_tot[ty][t];
    float* dstb = (q < 3)
        ? g_satc + (size_t)(b * Cc + q) * SST + BOFF
        : g_sata + (size_t)b * SST + BOFF;
    const int r = rblk * 16 + ty;

    #pragma unroll
    for (int j = 0; j < 16; j++) {
        float o = (t == 0) ? px[j] : __fadd_rn(carry, px[j]);
        int a = t * 16 + j;
        dstb[(size_t)(a + 1) * RPT + (r + 1)] = o;
    }

    if (rblk == 0) {
        for (int i = tid; i < 513; i += 512) {
            dstb[i] = 0.f;
            dstb[(size_t)i * RPT] = 0.f;
        }
    }
}

// ---------------- K3: per-detection vals, argmax, prb (transposed SAT) ------
__global__ void __launch_bounds__(192) k_detect(
    const int* __restrict__ det_b, const int* __restrict__ det_c,
    const int* __restrict__ det_r, const int* __restrict__ det_a,
    const int* __restrict__ radus, const float* __restrict__ pred,
    float* __restrict__ out)
{
    const int g = blockIdx.x;
    const int t = threadIdx.x;

    __shared__ float v3[Kc][NS];
    __shared__ float se[NS];
    __shared__ int   s_shift;
    __shared__ float s_pm[12];

    if (t < Kc * NS) {
        const int k  = t / NS;
        const int s  = t % NS;
        const int sh = s - 20;
        const int gk = g * Kc + k;
        const int dr = det_r[gk], da = det_a[gk], db = det_b[gk];
        const int dc = det_c[gk], rad = radus[gk];

        const int rc = dr + sh;
        const int r1 = min(max(rc - rad, 0), Rc);
        const int r2 = min(max(rc + rad + 1, 0), Rc);
        const int a1 = min(max(da - 2, 0), Ac);
        const int a2 = min(max(da + 3, 0), Ac);

        float xw = __fdiv_rn(-(float)(sh < 0 ? -sh : sh), 200.0f);
        float w  = (float)exp((double)xw);

        const float* sc = g_satc + (size_t)(db * Cc + dc) * SST + BOFF;
        const float* sa = g_sata + (size_t)db * SST + BOFF;

        float c22 = sc[(size_t)a2 * RPT + r2], c12 = sc[(size_t)a2 * RPT + r1];
        float c21 = sc[(size_t)a1 * RPT + r2], c11 = sc[(size_t)a1 * RPT + r1];
        float rect4 = __fadd_rn(__fsub_rn(__fsub_rn(c22, c12), c21), c11);
        float val1  = __fmul_rn(rect4, w);

        float d22 = sa[(size_t)a2 * RPT + r2], d12 = sa[(size_t)a2 * RPT + r1];
        float d21 = sa[(size_t)a1 * RPT + r2], d11 = sa[(size_t)a1 * RPT + r1];
        float rect3 = __fadd_rn(__fsub_rn(__fsub_rn(d22, d12), d21), d11);
        float val2  = __fmul_rn(rect3, w);

        float val3 = __fadd_rn(__fmul_rn(0.5f, val1),
                               __fmul_rn(0.5f, __fsub_rn(val2, val1)));
        v3[k][s] = val3;
    }
    __syncthreads();

    if (t < NS) {
        float s0 = __fadd_rn(__fadd_rn(__fadd_rn(v3[0][t], v3[1][t]), v3[2][t]), v3[3][t]);
        se[t] = s0;
        out[(size_t)g * NS + t] = s0;
    }
    __syncthreads();

    if (t == 0) {
        float best = se[0];
        int bi = 0;
        #pragma unroll
        for (int i = 1; i < NS; i++)
            if (se[i] > best) { best = se[i]; bi = i; }   // first occurrence
        s_shift = bi - 20;
        out[(size_t)Gc * NS       + g] = (float)(bi - 20);
        out[(size_t)Gc * (NS + 1) + g] = best;
    }
    __syncthreads();

    if (t < 12) {   // parallel prb_max gather: kk = t/3, c = t%3
        const int kk = t / 3, c = t % 3;
        const int gg = g * Kc + kk;
        const int rr = min(max(det_r[gg] + s_shift, 0), Rc - 1);
        const int db = det_b[gg], da = det_a[gg];
        s_pm[t] = __ldg(pred + (((size_t)db * Cc + c) * Rc + rr) * Ac + da);
    }
    __syncthreads();

    if (t == 0) {
        float pm = 0.3f;   // SMALL_PROB
        #pragma unroll
        for (int i = 0; i < 12; i++) pm = fmaxf(pm, s_pm[i]);
        out[(size_t)Gc * (NS + 2) + g] = pm;
    }
}

extern "C" void kernel_launch(void* const* d_in, const int* in_sizes, int n_in,
                              void* d_out, int out_size)
{
    const float* pred  = (const float*)d_in[0];
    const int*   det_b = (const int*)  d_in[1];
    const int*   det_c = (const int*)  d_in[2];
    const int*   det_r = (const int*)  d_in[3];
    const int*   det_a = (const int*)  d_in[4];
    const int*   radus = (const int*)  d_in[5];
    float*       out   = (float*)d_out;

    k_rowscan<<<Bc * (Ac / 32), 1024>>>(pred);        // 256 blocks, all 4 q fused
    k_colscan<<<Bc * Qc * 32, 512>>>();               // 16-row stripes
    k_detect<<<Gc, 192>>>(det_b, det_c, det_r, det_a, radus, pred, out);
}

// round 9
// speedup vs baseline: 4.3706x; 1.3107x over previous
#include <cuda_runtime.h>
#include <math.h>

#define Bc   16
#define Cc   3
#define Rc   512
#define Ac   512
#define Gc   4096
#define Kc   4
#define NS   41     // shifts -20..+20
#define Qc   4      // 3 channels + channel-sum

// Transposed SAT layout: value SAT[r][a] stored at slice[BOFF + a*RPT + r]
#define RPT  544                 // padded row stride (a-major), 32-aligned
#define BOFF 31                  // base offset so (r+1+BOFF) is 32-aligned
#define SST  (513 * RPT + 64)    // slice stride (elements), 32-aligned

// Static scratch
__device__ float g_y[(size_t)Bc * Qc * Rc * Ac];    // row-cumsum: q=0..2 channels, q=3 chan-sum
__device__ float g_satc[(size_t)Bc * Cc * SST];     // transposed per-channel SAT
__device__ float g_sata[(size_t)Bc * SST];          // transposed channel-sum SAT
__device__ float g_w[NS];                           // w[s] = exp(-|s-20|/200), fp32

// ---- one XLA ReduceWindowRewriter(base=16) scan over 512 elems, in-block ---
__device__ __forceinline__ void scan_block(float (&px)[16], float* dst,
                                           int t, int tx, float (*s_tot)[33])
{
    #pragma unroll
    for (int j = 1; j < 16; j++) px[j] = __fadd_rn(px[j-1], px[j]);
    s_tot[t][tx] = px[15];
    __syncthreads();

    if (t == 0) {
        float acc = s_tot[0][tx];                    // incT[0]
        #pragma unroll
        for (int t2 = 1; t2 < 16; t2++) {
            float T = s_tot[t2][tx];
            s_tot[t2][tx] = acc;                     // carry[t2] = incT[t2-1]
            acc = __fadd_rn(acc, T);
        }
        float U0  = acc;                             // fold of T[0..15]
        float T16 = s_tot[16][tx];
        s_tot[16][tx] = acc;                         // carry[16] = incT[15]
        float acch = T16;
        acc = __fadd_rn(U0, acch);                   // incT[16]
        #pragma unroll
        for (int t2 = 17; t2 < 32; t2++) {
            float T = s_tot[t2][tx];
            s_tot[t2][tx] = acc;                     // carry[t2] = incT[t2-1]
            acch = __fadd_rn(acch, T);
            acc = __fadd_rn(U0, acch);
        }
    }
    __syncthreads();

    const float carry = s_tot[t][tx];
    #pragma unroll
    for (int j = 0; j < 16; j++) {
        float o = (t == 0) ? px[j] : __fadd_rn(carry, px[j]);
        dst[(size_t)j * Ac] = o;
    }
    __syncthreads();   // s_tot reused by next scan
}

// ---------------- K1: fused row-axis scans — single pred read ---------------
__global__ void __launch_bounds__(1024) k_rowscan(const float* __restrict__ pred)
{
    // block 0 additionally materializes the w table (identical instruction
    // sequence as before -> identical bits)
    if (blockIdx.x == 0 && threadIdx.x < NS) {
        const int sh = (int)threadIdx.x - 20;
        float xw = __fdiv_rn(-(float)(sh < 0 ? -sh : sh), 200.0f);
        g_w[threadIdx.x] = (float)exp((double)xw);
    }

    const int blk  = blockIdx.x;          // 0..255
    const int acol = blk & 15;
    const int b    = blk >> 4;
    const int tx   = threadIdx.x & 31;
    const int t    = threadIdx.x >> 5;    // tile 0..31
    const int a    = acol * 32 + tx;

    __shared__ float s_tot[32][33];

    const float* p  = pred + ((size_t)b * Cc * Rc) * Ac + a;
    float*       yb = g_y  + ((size_t)b * Qc * Rc) * Ac + a;

    float ps[16];   // running channel sum (raw), exact (v0+v1)+v2 order

    #pragma unroll
    for (int c = 0; c < 3; c++) {
        float px[16];
        const float* pc = p + ((size_t)c * Rc + (size_t)t * 16) * Ac;
        #pragma unroll
        for (int j = 0; j < 16; j++) px[j] = __ldg(pc + (size_t)j * Ac);
        #pragma unroll
        for (int j = 0; j < 16; j++)
            ps[j] = (c == 0) ? px[j] : __fadd_rn(ps[j], px[j]);
        scan_block(px, yb + ((size_t)c * Rc + (size_t)t * 16) * Ac, t, tx, s_tot);
    }
    scan_block(ps, yb + ((size_t)3 * Rc + (size_t)t * 16) * Ac, t, tx, s_tot);
}

// ---------------- K2: col-axis scans -> TRANSPOSED SAT ----------------------
__global__ void __launch_bounds__(512) k_colscan()
{
    const int blk  = blockIdx.x;           // (b,q,rblk): 16*4*32
    const int rblk = blk & 31;
    const int q    = (blk >> 5) & 3;
    const int b    = blk >> 7;
    const int tid  = threadIdx.x;
    const int ty   = tid & 15;              // row in stripe
    const int t    = tid >> 4;              // a-tile 0..31

    __shared__ float s_in[16][545];
    __shared__ float s_tot[16][33];

    const float* src = g_y + (((size_t)b * Qc + q) * Rc + (size_t)rblk * 16) * Ac;

    #pragma unroll
    for (int i = 0; i < 16; i++) {
        int idx = i * 512 + tid;
        int rr = idx >> 9, cc = idx & 511;
        s_in[rr][cc + (cc >> 4)] = src[(size_t)rr * Ac + cc];
    }
    __syncthreads();

    float px[16];
    #pragma unroll
    for (int j = 0; j < 16; j++) px[j] = s_in[ty][17 * t + j];
    #pragma unroll
    for (int j = 1; j < 16; j++) px[j] = __fadd_rn(px[j-1], px[j]);
    s_tot[ty][t] = px[15];
    __syncthreads();

    if (t == 0) {
        float acc = s_tot[ty][0];
        #pragma unroll
        for (int t2 = 1; t2 < 16; t2++) {
            float T = s_tot[ty][t2];
            s_tot[ty][t2] = acc;
            acc = __fadd_rn(acc, T);
        }
        float U0  = acc;
        float T16 = s_tot[ty][16];
        s_tot[ty][16] = acc;
        float acch = T16;
        acc = __fadd_rn(U0, acch);
        #pragma unroll
        for (int t2 = 17; t2 < 32; t2++) {
            float T = s_tot[ty][t2];
            s_tot[ty][t2] = acc;
            acch = __fadd_rn(acch, T);
            acc = __fadd_rn(U0, acch);
        }
    }
    __syncthreads();

    const float carry = s_tot[ty][t];
    float* dstb = (q < 3)
        ? g_satc + (size_t)(b * Cc + q) * SST + BOFF
        : g_sata + (size_t)b * SST + BOFF;
    const int r = rblk * 16 + ty;

    #pragma unroll
    for (int j = 0; j < 16; j++) {
        float o = (t == 0) ? px[j] : __fadd_rn(carry, px[j]);
        int a = t * 16 + j;
        dstb[(size_t)(a + 1) * RPT + (r + 1)] = o;
    }

    if (rblk == 0) {
        for (int i = tid; i < 513; i += 512) {
            dstb[i] = 0.f;
            dstb[(size_t)i * RPT] = 0.f;
        }
    }
}

// ---------------- K3: per-detection vals; warp-0 epilogue -------------------
__global__ void __launch_bounds__(192) k_detect(
    const int* __restrict__ det_b, const int* __restrict__ det_c,
    const int* __restrict__ det_r, const int* __restrict__ det_a,
    const int* __restrict__ radus, const float* __restrict__ pred,
    float* __restrict__ out)
{
    const int g = blockIdx.x;
    const int t = threadIdx.x;

    __shared__ float v3[Kc][NS];

    if (t < Kc * NS) {
        const int k  = t / NS;
        const int s  = t % NS;
        const int sh = s - 20;
        const int gk = g * Kc + k;
        const int dr = det_r[gk], da = det_a[gk], db = det_b[gk];
        const int dc = det_c[gk], rad = radus[gk];

        const int rc = dr + sh;
        const int r1 = min(max(rc - rad, 0), Rc);
        const int r2 = min(max(rc + rad + 1, 0), Rc);
        const int a1 = min(max(da - 2, 0), Ac);
        const int a2 = min(max(da + 3, 0), Ac);

        const float w = g_w[s];

        const float* sc = g_satc + (size_t)(db * Cc + dc) * SST + BOFF;
        const float* sa = g_sata + (size_t)db * SST + BOFF;

        float c22 = __ldg(sc + (size_t)a2 * RPT + r2), c12 = __ldg(sc + (size_t)a2 * RPT + r1);
        float c21 = __ldg(sc + (size_t)a1 * RPT + r2), c11 = __ldg(sc + (size_t)a1 * RPT + r1);
        float rect4 = __fadd_rn(__fsub_rn(__fsub_rn(c22, c12), c21), c11);
        float val1  = __fmul_rn(rect4, w);

        float d22 = __ldg(sa + (size_t)a2 * RPT + r2), d12 = __ldg(sa + (size_t)a2 * RPT + r1);
        float d21 = __ldg(sa + (size_t)a1 * RPT + r2), d11 = __ldg(sa + (size_t)a1 * RPT + r1);
        float rect3 = __fadd_rn(__fsub_rn(__fsub_rn(d22, d12), d21), d11);
        float val2  = __fmul_rn(rect3, w);

        float val3 = __fadd_rn(__fmul_rn(0.5f, val1),
                               __fmul_rn(0.5f, __fsub_rn(val2, val1)));
        v3[k][s] = val3;
    }
    __syncthreads();

    if (t < 32) {   // warp 0 does the whole epilogue, no more block syncs
        const int s1 = t;
        float bv, se1;
        int   bi = s1;
        se1 = __fadd_rn(__fadd_rn(__fadd_rn(v3[0][s1], v3[1][s1]), v3[2][s1]), v3[3][s1]);
        out[(size_t)g * NS + s1] = se1;
        bv = se1;
        const int s2 = t + 32;
        if (s2 < NS) {
            float se2 = __fadd_rn(__fadd_rn(__fadd_rn(v3[0][s2], v3[1][s2]), v3[2][s2]), v3[3][s2]);
            out[(size_t)g * NS + s2] = se2;
            if (se2 > bv) { bv = se2; bi = s2; }   // strictly greater: keep first
        }
        // warp first-max reduce: keep lower index on ties
        #pragma unroll
        for (int off = 16; off > 0; off >>= 1) {
            float ov = __shfl_xor_sync(0xffffffffu, bv, off);
            int   oi = __shfl_xor_sync(0xffffffffu, bi, off);
            if (ov > bv || (ov == bv && oi < bi)) { bv = ov; bi = oi; }
        }
        const int shift = bi - 20;

        float pmv = 0.3f;   // SMALL_PROB floor
        if (t < 12) {       // kk = t/3, c = t%3
            const int kk = t / 3, c = t % 3;
            const int gg = g * Kc + kk;
            const int rr = min(max(det_r[gg] + shift, 0), Rc - 1);
            const int db = det_b[gg], da = det_a[gg];
            pmv = fmaxf(pmv, __ldg(pred + (((size_t)db * Cc + c) * Rc + rr) * Ac + da));
        }
        #pragma unroll
        for (int off = 16; off > 0; off >>= 1)
            pmv = fmaxf(pmv, __shfl_xor_sync(0xffffffffu, pmv, off));

        if (t == 0) {
            out[(size_t)Gc * NS       + g] = (float)shift;
            out[(size_t)Gc * (NS + 1) + g] = bv;
            out[(size_t)Gc * (NS + 2) + g] = pmv;
        }
    }
}

extern "C" void kernel_launch(void* const* d_in, const int* in_sizes, int n_in,
                              void* d_out, int out_size)
{
    const float* pred  = (const float*)d_in[0];
    const int*   det_b = (const int*)  d_in[1];
    const int*   det_c = (const int*)  d_in[2];
    const int*   det_r = (const int*)  d_in[3];
    const int*   det_a = (const int*)  d_in[4];
    const int*   radus = (const int*)  d_in[5];
    float*       out   = (float*)d_out;

    k_rowscan<<<Bc * (Ac / 32), 1024>>>(pred);        // 256 blocks, all 4 q fused (+ w table)
    k_colscan<<<Bc * Qc * 32, 512>>>();               // 16-row stripes
    k_detect<<<Gc, 192>>>(det_b, det_c, det_r, det_a, radus, pred, out);
}